// round 5
// baseline (speedup 1.0000x reference)
#include <cuda_runtime.h>
#include <cstdint>

#define DDIM 64
#define KCODES 1024
#define NTOK 131072
#define TM 128
#define NTHREADS 128
#define NCHUNKS 16
#define CCHUNK 64
#define CAP 8
#define MARGIN 0.008f

#define ROWW 72                         // words per fragment row (288B, bank-safe)
#define CHUNK_BYTES (CCHUNK * ROWW * 4) // 18432

// ---------------- smem layout (bytes) ----------------
#define OFF_XF   0                      // float [128][65] = 33280
#define OFF_CN   33280                  // float [1024]    = 4096
#define OFF_CAND 37376                  // int [128][32]   = 16384
#define OFF_XNS  53760                  // float [128]
#define OFF_WIX  54272                  // int [128]
#define OFF_OFL  54784                  // int [128]
#define OFF_B    55296                  // 3 x 18432 = 55296
#define SMEM_BYTES (OFF_B + 3 * CHUNK_BYTES)   // 110592

__device__ float g_cn[KCODES];
__device__ __align__(256) uint32_t g_bT[KCODES * ROWW];  // tf32, fragment order

__device__ __forceinline__ uint32_t f2tf(float x) {
    uint32_t r;
    asm("cvt.rna.tf32.f32 %0, %1;" : "=r"(r) : "f"(x));
    return r;
}

// prep: ||c||^2 (exact seq order) + fragment-ordered tf32 codebook
__global__ void vq_prep(const float* __restrict__ cb) {
    int r = blockIdx.x * blockDim.x + threadIdx.x;
    if (r >= KCODES) return;
    const float* cr = cb + r * DDIM;
    float acc = 0.f;
#pragma unroll
    for (int d = 0; d < DDIM; d++) acc = __fadd_rn(acc, __fmul_rn(cr[d], cr[d]));
    g_cn[r] = acc;
    const int qoff[4] = {0, 16, 36, 52};
#pragma unroll
    for (int q = 0; q < 4; q++)
#pragma unroll
        for (int kc = 0; kc < 8; kc++) {
            g_bT[r * ROWW + qoff[q] + kc * 2 + 0] = f2tf(cr[kc * 8 + q]);
            g_bT[r * ROWW + qoff[q] + kc * 2 + 1] = f2tf(cr[kc * 8 + q + 4]);
        }
#pragma unroll
    for (int p = 68; p < 72; p++) g_bT[r * ROWW + p] = 0;
}

__device__ __forceinline__ void mma_tf32(float* c, const uint32_t* a,
                                         uint32_t b0, uint32_t b1) {
    asm volatile(
        "mma.sync.aligned.m16n8k8.row.col.f32.tf32.tf32.f32 "
        "{%0,%1,%2,%3}, {%4,%5,%6,%7}, {%8,%9}, {%0,%1,%2,%3};"
        : "+f"(c[0]), "+f"(c[1]), "+f"(c[2]), "+f"(c[3])
        : "r"(a[0]), "r"(a[1]), "r"(a[2]), "r"(a[3]), "r"(b0), "r"(b1));
}
__device__ __forceinline__ void lds128(uint4& v, uint32_t a) {
    asm volatile("ld.shared.v4.u32 {%0,%1,%2,%3}, [%4];"
                 : "=r"(v.x), "=r"(v.y), "=r"(v.z), "=r"(v.w) : "r"(a));
}
__device__ __forceinline__ uint32_t smem_u32(const void* p) {
    uint32_t a;
    asm("{ .reg .u64 t; cvta.to.shared.u64 t, %1; cvt.u32.u64 %0, t; }" : "=r"(a) : "l"(p));
    return a;
}
__device__ __forceinline__ void issue_chunk(uint32_t dst, const char* src) {
#pragma unroll
    for (int k = 0; k < 9; k++) {
        int off = (threadIdx.x + k * NTHREADS) * 16;
        asm volatile("cp.async.ca.shared.global [%0], [%1], 16;"
                     :: "r"(dst + off), "l"(src + off) : "memory");
    }
    asm volatile("cp.async.commit_group;" ::: "memory");
}
__device__ __forceinline__ void cp_wait(int rem) {
    if (rem >= 2)      asm volatile("cp.async.wait_group 2;" ::: "memory");
    else if (rem == 1) asm volatile("cp.async.wait_group 1;" ::: "memory");
    else               asm volatile("cp.async.wait_group 0;" ::: "memory");
}

// exact rescore: bit-matches reference (R2/R4-verified)
__device__ __forceinline__ float exact_d2(const float* __restrict__ cb,
                                          const float* __restrict__ xrow,
                                          float xn, float cnk, int k) {
    const float4* cr = (const float4*)(cb + k * DDIM);
    float s = 0.f;
#pragma unroll
    for (int i = 0; i < 16; i++) {
        float4 v = cr[i];
        s = __fmaf_rn(xrow[4 * i + 0], v.x, s);
        s = __fmaf_rn(xrow[4 * i + 1], v.y, s);
        s = __fmaf_rn(xrow[4 * i + 2], v.z, s);
        s = __fmaf_rn(xrow[4 * i + 3], v.w, s);
    }
    return __fadd_rn(__fsub_rn(xn, __fmul_rn(2.0f, s)), cnk);
}

__global__ __launch_bounds__(NTHREADS, 2)
void vq_main(const float* __restrict__ h, const float* __restrict__ cb,
             float* __restrict__ outZ, float* __restrict__ outQ) {
    extern __shared__ char smem[];
    float* Xf   = (float*)(smem + OFF_XF);
    float* Cn   = (float*)(smem + OFF_CN);
    int*   cand = (int*)(smem + OFF_CAND);
    float* xns  = (float*)(smem + OFF_XNS);
    int*   wix  = (int*)(smem + OFF_WIX);
    int*   ofl  = (int*)(smem + OFF_OFL);
    const uint32_t sbase = smem_u32(smem);

    const int tid = threadIdx.x;
    const int wid = tid >> 5;
    const int lid = tid & 31;
    const int g = lid >> 2;
    const int q = lid & 3;
    const int tw = wid * 32;
    const int n0 = blockIdx.x * TM;
    const int b = n0 >> 12;
    const long base = (long)b * 262144 + (n0 & 4095);

    // prefetch B chunks 0..2 first (overlap with everything below)
#pragma unroll
    for (int c = 0; c < 3; c++)
        issue_chunk(sbase + OFF_B + c * CHUNK_BYTES, (const char*)g_bT + c * CHUNK_BYTES);

    // Xf exact fp32 tile (coalesced d-major)
    for (int i = tid; i < 64 * 16; i += NTHREADS) {
        int d = i >> 4, t8 = i & 15;
        float4 v0 = *(const float4*)(h + base + (long)d * 4096 + t8 * 8);
        float4 v1 = *(const float4*)(h + base + (long)d * 4096 + t8 * 8 + 4);
        Xf[(t8 * 8 + 0) * 65 + d] = v0.x; Xf[(t8 * 8 + 1) * 65 + d] = v0.y;
        Xf[(t8 * 8 + 2) * 65 + d] = v0.z; Xf[(t8 * 8 + 3) * 65 + d] = v0.w;
        Xf[(t8 * 8 + 4) * 65 + d] = v1.x; Xf[(t8 * 8 + 5) * 65 + d] = v1.y;
        Xf[(t8 * 8 + 6) * 65 + d] = v1.z; Xf[(t8 * 8 + 7) * 65 + d] = v1.w;
    }
    for (int i = tid; i < KCODES; i += NTHREADS) Cn[i] = g_cn[i];
    ofl[tid] = 0;
    __syncthreads();

    // exact xn (sequential mul-then-add, reference order)
    {
        float acc = 0.f;
#pragma unroll
        for (int d = 0; d < 64; d++) {
            float xv = Xf[tid * 65 + d];
            acc = __fadd_rn(acc, __fmul_rn(xv, xv));
        }
        xns[tid] = acc;
    }

    // A fragments for 32 tokens (2 x m16 sets), registers for whole kernel
    uint32_t afr0[32], afr1[32];
    {
        const float* xr = &Xf[(tw + g) * 65];
#pragma unroll
        for (int kc = 0; kc < 8; kc++) {
            int d0 = kc * 8 + q, d1 = d0 + 4;
            afr0[kc * 4 + 0] = f2tf(xr[d0]);
            afr0[kc * 4 + 1] = f2tf(xr[8 * 65 + d0]);
            afr0[kc * 4 + 2] = f2tf(xr[d1]);
            afr0[kc * 4 + 3] = f2tf(xr[8 * 65 + d1]);
            afr1[kc * 4 + 0] = f2tf(xr[16 * 65 + d0]);
            afr1[kc * 4 + 1] = f2tf(xr[24 * 65 + d0]);
            afr1[kc * 4 + 2] = f2tf(xr[16 * 65 + d1]);
            afr1[kc * 4 + 3] = f2tf(xr[24 * 65 + d1]);
        }
    }
    __syncthreads();

    float xnv[4], best[4];
    int cnt[4];
#pragma unroll
    for (int s = 0; s < 4; s++) {
        xnv[s] = xns[tw + g + s * 8];
        best[s] = 3.4e38f;
        cnt[s] = 0;
    }
    const uint32_t qoffB = (uint32_t)(q * 64 + (q >> 1) * 16);

#pragma unroll 1
    for (int c = 0; c < NCHUNKS; c++) {
        int rem = 15 - c;
        cp_wait(rem >= 2 ? 2 : rem);
        __syncthreads();

        const uint32_t bb = sbase + OFF_B + (c % 3) * CHUNK_BYTES;
        const int cbase = c * CCHUNK;

#pragma unroll
        for (int hh = 0; hh < 2; hh++) {
            uint4 bf[4][4];
#pragma unroll
            for (int jj = 0; jj < 4; jj++) {
                uint32_t a = bb + (uint32_t)(((hh * 4 + jj) * 8 + g) * 288) + qoffB;
                lds128(bf[jj][0], a);
                lds128(bf[jj][1], a + 16);
                lds128(bf[jj][2], a + 32);
                lds128(bf[jj][3], a + 48);
            }
            float acc0[4][4], acc1[4][4];
#pragma unroll
            for (int jj = 0; jj < 4; jj++)
#pragma unroll
                for (int e = 0; e < 4; e++) { acc0[jj][e] = 0.f; acc1[jj][e] = 0.f; }

#pragma unroll
            for (int kc = 0; kc < 8; kc++) {
#pragma unroll
                for (int jj = 0; jj < 4; jj++) {
                    uint4 bv = bf[jj][kc >> 1];
                    uint32_t b0 = (kc & 1) ? bv.z : bv.x;
                    uint32_t b1 = (kc & 1) ? bv.w : bv.y;
                    mma_tf32(acc0[jj], afr0 + kc * 4, b0, b1);
                    mma_tf32(acc1[jj], afr1 + kc * 4, b0, b1);
                }
            }

            // epilogue: approx d2, candidate collection (per token slot)
#pragma unroll
            for (int jj = 0; jj < 4; jj++) {
                int k0 = cbase + (hh * 4 + jj) * 8 + q * 2;
                float2 cn2 = *(const float2*)&Cn[k0];
#pragma unroll
                for (int s = 0; s < 4; s++) {
                    float v0 = (s < 2) ? acc0[jj][(s & 1) * 2]     : acc1[jj][(s & 1) * 2];
                    float v1 = (s < 2) ? acc0[jj][(s & 1) * 2 + 1] : acc1[jj][(s & 1) * 2 + 1];
                    float a0 = xnv[s] - 2.0f * v0 + cn2.x;
                    float a1 = xnv[s] - 2.0f * v1 + cn2.y;
                    float pm = fminf(a0, a1);
                    if (pm < best[s] + MARGIN) {
                        int t = tw + g + s * 8;
                        if (a0 < best[s] + MARGIN) {
                            if (cnt[s] < CAP) cand[t * 32 + q * 8 + cnt[s]] = k0;
                            else ofl[t] = 1;
                            cnt[s]++;
                        }
                        if (a1 < best[s] + MARGIN) {
                            if (cnt[s] < CAP) cand[t * 32 + q * 8 + cnt[s]] = k0 + 1;
                            else ofl[t] = 1;
                            cnt[s]++;
                        }
                        best[s] = fminf(best[s], pm);
                    }
                }
            }
        }
        // tighten bests across the quad (same tokens share g)
#pragma unroll
        for (int s = 0; s < 4; s++) {
            best[s] = fminf(best[s], __shfl_xor_sync(0xffffffffu, best[s], 1));
            best[s] = fminf(best[s], __shfl_xor_sync(0xffffffffu, best[s], 2));
        }
        __syncthreads();
        if (c + 3 < NCHUNKS)
            issue_chunk(sbase + OFF_B + (c % 3) * CHUNK_BYTES,
                        (const char*)g_bT + (c + 3) * CHUNK_BYTES);
    }

    // exact rescore (bit-matches reference); quad combine with lowest-index tie-break
#pragma unroll
    for (int s = 0; s < 4; s++) {
        int t = tw + g + s * 8;
        const float* xrow = &Xf[t * 65];
        float xn = xnv[s];
        float bv = 3.4e38f;
        int bi = 0x7fffffff;
        if (ofl[t]) {
            for (int k = q; k < KCODES; k += 4) {
                float d2 = exact_d2(cb, xrow, xn, Cn[k], k);
                if (d2 < bv || (d2 == bv && k < bi)) { bv = d2; bi = k; }
            }
        } else {
            for (int i = 0; i < cnt[s]; i++) {
                int k = cand[t * 32 + q * 8 + i];
                float d2 = exact_d2(cb, xrow, xn, Cn[k], k);
                if (d2 < bv || (d2 == bv && k < bi)) { bv = d2; bi = k; }
            }
        }
#pragma unroll
        for (int off = 1; off < 4; off <<= 1) {
            float ov = __shfl_xor_sync(0xffffffffu, bv, off);
            int oi = __shfl_xor_sync(0xffffffffu, bi, off);
            if (ov < bv || (ov == bv && oi < bi)) { bv = ov; bi = oi; }
        }
        if (q == 0) {
            wix[t] = bi;
            if (outZ) outZ[n0 + t] = (float)bi;
        }
    }
    __syncthreads();

    if (outQ) {
        for (int i = tid; i < 128 * 16; i += NTHREADS) {
            int tt = i >> 4, c4 = i & 15;
            float4 v = *(const float4*)&cb[wix[tt] * DDIM + c4 * 4];
            *(float4*)&outQ[(long)(n0 + tt) * DDIM + c4 * 4] = v;
        }
    }
}

extern "C" void kernel_launch(void* const* d_in, const int* in_sizes, int n_in,
                              void* d_out, int out_size) {
    const float* h = (const float*)d_in[0];
    const float* cb = (const float*)d_in[1];
    float* out = (float*)d_out;

    float* outZ = nullptr;
    float* outQ = nullptr;
    if (out_size >= NTOK + NTOK * DDIM) { outZ = out; outQ = out + NTOK; }
    else if (out_size == NTOK * DDIM)   { outQ = out; }
    else                                { outZ = out; }

    cudaFuncSetAttribute(vq_main, cudaFuncAttributeMaxDynamicSharedMemorySize, SMEM_BYTES);
    vq_prep<<<4, 256>>>(cb);
    vq_main<<<NTOK / TM, NTHREADS, SMEM_BYTES>>>(h, cb, outZ, outQ);
}